// round 1
// baseline (speedup 1.0000x reference)
#include <cuda_runtime.h>
#include <cstdint>

#define NN 200000
#define EE 8192
#define HH 64
#define EAA 32
#define AA 50
#define DF 128

#define NBLK 148
#define NTHR 512
#define NWARP (NTHR / 32)
#define TOTWARP (NBLK * NWARP)
#define MAXWAVES 48

// ---- shared memory layout (floats) ----
#define WMT_STRIDE 196
#define OFF_WMT 0
#define SZ_WMT (64 * WMT_STRIDE)            // 12544 (W_msg transposed [64+? rows][196])
#define OFF_WIH (OFF_WMT + SZ_WMT)          // 12544
#define OFF_WHH (OFF_WIH + 16384)           // 28928
#define OFF_BM  (OFF_WHH + 16384)           // 45312
#define OFF_BL  (OFF_BM + 64)               // 45376
#define OFF_TW  (OFF_BL + 256)              // 45632
#define OFF_TB  (OFF_TW + 32)               // 45664
#define OFF_FEAT (OFF_TB + 32)              // 45696
#define OFF_M   (OFF_FEAT + NWARP * 192)    // 48768
#define SMEM_FLOATS (OFF_M + NWARP * 128)   // 50816
#define SMEM_BYTES (SMEM_FLOATS * 4)        // 203264

// ---- device scratch ----
__device__ float g_h[(size_t)NN * HH];
__device__ float g_c[(size_t)NN * HH];
__device__ int   g_nodemin[NN];
__device__ int   g_done[EE];
__device__ float g_Wc[192 * AA];
__device__ float g_bc[AA];
__device__ int   g_remaining;
__device__ unsigned g_bar_cnt;
__device__ volatile unsigned g_bar_gen;

__device__ __forceinline__ void grid_bar() {
    __syncthreads();
    if (threadIdx.x == 0) {
        __threadfence();
        unsigned gen = g_bar_gen;
        if (atomicAdd(&g_bar_cnt, 1u) == (unsigned)(gridDim.x - 1u)) {
            g_bar_cnt = 0u;
            __threadfence();
            g_bar_gen = gen + 1u;
        } else {
            while (g_bar_gen == gen) __nanosleep(128);
            __threadfence();
        }
    }
    __syncthreads();
}

__device__ __forceinline__ float sigf(float v) { return 1.0f / (1.0f + __expf(-v)); }
__device__ __forceinline__ float tanhf_(float v) {
    float e = __expf(2.0f * v);
    return 1.0f - 2.0f / (e + 1.0f);
}

#define FMA4(acc, f, wv)                     \
    acc = fmaf((f).x, (wv).x, acc);          \
    acc = fmaf((f).y, (wv).y, acc);          \
    acc = fmaf((f).z, (wv).z, acc);          \
    acc = fmaf((f).w, (wv).w, acc);

#define LSTM_STEP(acc, mm, hv, wA, wB, uA, uB)        \
    acc[0] = fmaf(mm, (wA).x, acc[0]);                \
    acc[1] = fmaf(mm, (wA).y, acc[1]);                \
    acc[2] = fmaf(mm, (wA).z, acc[2]);                \
    acc[3] = fmaf(mm, (wA).w, acc[3]);                \
    acc[4] = fmaf(mm, (wB).x, acc[4]);                \
    acc[5] = fmaf(mm, (wB).y, acc[5]);                \
    acc[6] = fmaf(mm, (wB).z, acc[6]);                \
    acc[7] = fmaf(mm, (wB).w, acc[7]);                \
    acc[0] = fmaf(hv, (uA).x, acc[0]);                \
    acc[1] = fmaf(hv, (uA).y, acc[1]);                \
    acc[2] = fmaf(hv, (uA).z, acc[2]);                \
    acc[3] = fmaf(hv, (uA).w, acc[3]);                \
    acc[4] = fmaf(hv, (uB).x, acc[4]);                \
    acc[5] = fmaf(hv, (uB).y, acc[5]);                \
    acc[6] = fmaf(hv, (uB).z, acc[6]);                \
    acc[7] = fmaf(hv, (uB).w, acc[7]);

// Process one event with one warp. Weights in smem. Feature/msg staging per warp.
__device__ void process_event(int e, int src, int dst, float* sm, float* sF, float* sMw,
                              int lane, const float* __restrict__ eattr,
                              const float* __restrict__ etime) {
    // ---- stage features: [0:64)=hs  [64:128)=hd  [128:160)=ea  [160:192)=te ----
    float t = etime[e];
    sF[lane]       = g_h[(size_t)src * HH + lane];
    sF[32 + lane]  = g_h[(size_t)src * HH + 32 + lane];
    sF[64 + lane]  = g_h[(size_t)dst * HH + lane];
    sF[96 + lane]  = g_h[(size_t)dst * HH + 32 + lane];
    sF[128 + lane] = eattr[(size_t)e * EAA + lane];
    sF[160 + lane] = cosf(fmaf(t, sm[OFF_TW + lane], sm[OFF_TB + lane]));
    __syncwarp();

    // ---- message GEMV: rows (feat0=[hd,hs,ea,te], feat1=[hs,hd,ea,te]) x W_msg[192,64]
    const float4* w0p = (const float4*)(sm + OFF_WMT + lane * WMT_STRIDE);
    const float4* w1p = (const float4*)(sm + OFF_WMT + (lane + 32) * WMT_STRIDE);
    const float4* fv = (const float4*)sF;
    float a00 = sm[OFF_BM + lane], a01 = sm[OFF_BM + 32 + lane];
    float a10 = a00, a11 = a01;
#pragma unroll
    for (int q = 0; q < 16; q++) {  // k in [0,64): feat0 -> hd, feat1 -> hs
        float4 w0 = w0p[q], w1 = w1p[q];
        float4 f0 = fv[16 + q], f1 = fv[q];
        FMA4(a00, f0, w0); FMA4(a01, f0, w1);
        FMA4(a10, f1, w0); FMA4(a11, f1, w1);
    }
#pragma unroll
    for (int q = 16; q < 32; q++) {  // k in [64,128): feat0 -> hs, feat1 -> hd
        float4 w0 = w0p[q], w1 = w1p[q];
        float4 f0 = fv[q - 16], f1 = fv[q];
        FMA4(a00, f0, w0); FMA4(a01, f0, w1);
        FMA4(a10, f1, w0); FMA4(a11, f1, w1);
    }
#pragma unroll
    for (int q = 32; q < 48; q++) {  // k in [128,192): shared ea/te
        float4 w0 = w0p[q], w1 = w1p[q];
        float4 f = fv[q];
        FMA4(a00, f, w0); FMA4(a01, f, w1);
        FMA4(a10, f, w0); FMA4(a11, f, w1);
    }
    sMw[lane]      = fmaxf(a00, 0.0f);
    sMw[32 + lane] = fmaxf(a01, 0.0f);
    sMw[64 + lane] = fmaxf(a10, 0.0f);
    sMw[96 + lane] = fmaxf(a11, 0.0f);
    __syncwarp();

    // ---- LSTM: g = m @ W_ih + hp @ W_hh + b  (lane covers gate cols [4l..4l+3] and [128+4l..])
    const float4* wih = (const float4*)(sm + OFF_WIH);
    const float4* whh = (const float4*)(sm + OFF_WHH);
    float acc0[8], acc1[8];
#pragma unroll
    for (int c2 = 0; c2 < 4; c2++) {
        acc0[c2]     = sm[OFF_BL + 4 * lane + c2];
        acc0[4 + c2] = sm[OFF_BL + 128 + 4 * lane + c2];
        acc1[c2] = acc0[c2];
        acc1[4 + c2] = acc0[4 + c2];
    }
#pragma unroll 8
    for (int k = 0; k < 64; k++) {
        float m0 = sMw[k], m1 = sMw[64 + k];
        float h0 = sF[k], h1 = sF[64 + k];
        float4 wA = wih[(k << 6) + lane], wB = wih[(k << 6) + 32 + lane];
        float4 uA = whh[(k << 6) + lane], uB = whh[(k << 6) + 32 + lane];
        LSTM_STEP(acc0, m0, h0, wA, wB, uA, uB);
        LSTM_STEP(acc1, m1, h1, wA, wB, uA, uB);
    }
    // lanes 0..15 hold i (acc[0..3]) and g (acc[4..7]); lanes 16..31 hold f and o
    float f0g[4], o0g[4], f1g[4], o1g[4];
#pragma unroll
    for (int c2 = 0; c2 < 4; c2++) {
        f0g[c2] = __shfl_down_sync(0xffffffffu, acc0[c2], 16);
        o0g[c2] = __shfl_down_sync(0xffffffffu, acc0[4 + c2], 16);
        f1g[c2] = __shfl_down_sync(0xffffffffu, acc1[c2], 16);
        o1g[c2] = __shfl_down_sync(0xffffffffu, acc1[4 + c2], 16);
    }
    if (lane < 16) {
        float4 c0 = *(const float4*)(g_c + (size_t)src * HH + 4 * lane);
        float4 c1 = *(const float4*)(g_c + (size_t)dst * HH + 4 * lane);
        float cn0[4], hn0[4], cn1[4], hn1[4];
        float c0a[4] = {c0.x, c0.y, c0.z, c0.w};
        float c1a[4] = {c1.x, c1.y, c1.z, c1.w};
#pragma unroll
        for (int c2 = 0; c2 < 4; c2++) {
            cn0[c2] = sigf(f0g[c2]) * c0a[c2] + sigf(acc0[c2]) * tanhf_(acc0[4 + c2]);
            hn0[c2] = sigf(o0g[c2]) * tanhf_(cn0[c2]);
            cn1[c2] = sigf(f1g[c2]) * c1a[c2] + sigf(acc1[c2]) * tanhf_(acc1[4 + c2]);
            hn1[c2] = sigf(o1g[c2]) * tanhf_(cn1[c2]);
        }
        if (src != dst) {  // if src==dst the dst (row 1) update wins, matching scatter
            *(float4*)(g_h + (size_t)src * HH + 4 * lane) = make_float4(hn0[0], hn0[1], hn0[2], hn0[3]);
            *(float4*)(g_c + (size_t)src * HH + 4 * lane) = make_float4(cn0[0], cn0[1], cn0[2], cn0[3]);
        }
        *(float4*)(g_h + (size_t)dst * HH + 4 * lane) = make_float4(hn1[0], hn1[1], hn1[2], hn1[3]);
        *(float4*)(g_c + (size_t)dst * HH + 4 * lane) = make_float4(cn1[0], cn1[1], cn1[2], cn1[3]);
    }
    __syncwarp();
}

// ---- init: zero touched h/c, reset node_min/done/barriers, fuse W_emb@W_cls ----
__global__ void k_init(const int* __restrict__ ei, const float* __restrict__ Wemb,
                       const float* __restrict__ bemb, const float* __restrict__ Wcls,
                       const float* __restrict__ bcls) {
    int t = blockIdx.x * blockDim.x + threadIdx.x;
    if (t < 2 * EE) {
        int v = ei[t];
        float4 z = make_float4(0.f, 0.f, 0.f, 0.f);
        float4* hp = (float4*)(g_h + (size_t)v * HH);
        float4* cp = (float4*)(g_c + (size_t)v * HH);
#pragma unroll
        for (int i = 0; i < 16; i++) { hp[i] = z; cp[i] = z; }
        g_nodemin[v] = 0x7fffffff;
    }
    if (t < EE) g_done[t] = 0;
    if (t < 192 * AA) {
        int k = t / AA, a = t - k * AA;
        float s = 0.0f;
        for (int j = 0; j < HH; j++) s = fmaf(Wemb[k * HH + j], Wcls[j * AA + a], s);
        g_Wc[t] = s;
    }
    if (t < AA) {
        float s = bcls[t];
        for (int j = 0; j < HH; j++) s = fmaf(bemb[j], Wcls[j * AA + t], s);
        g_bc[t] = s;
    }
    if (t == 0) {
        g_remaining = EE;
        g_bar_cnt = 0u;
        g_bar_gen = 0u;
    }
}

// ---- persistent: wave-parallel event processing + fused classifier ----
__global__ void __launch_bounds__(NTHR, 1) k_persist(
    const float* __restrict__ x, const int* __restrict__ ei, const float* __restrict__ eattr,
    const float* __restrict__ etime, const float* __restrict__ tw, const float* __restrict__ tb,
    const float* __restrict__ Wmsg, const float* __restrict__ bmsg,
    const float* __restrict__ Wih, const float* __restrict__ Whh,
    const float* __restrict__ blstm, float* __restrict__ out) {
    extern __shared__ float sm[];
    const int tid = threadIdx.x;
    const int lane = tid & 31;
    const int wid = tid >> 5;

    // load weights to smem (W_msg transposed with padded stride for conflict-free LDS.128)
    for (int i = tid; i < 192 * 64; i += NTHR) {
        int k = i >> 6, j = i & 63;
        sm[OFF_WMT + j * WMT_STRIDE + k] = Wmsg[i];
    }
    {
        float4* d1 = (float4*)(sm + OFF_WIH);
        float4* d2 = (float4*)(sm + OFF_WHH);
        const float4* s1 = (const float4*)Wih;
        const float4* s2 = (const float4*)Whh;
        for (int i = tid; i < 4096; i += NTHR) { d1[i] = s1[i]; d2[i] = s2[i]; }
    }
    for (int i = tid; i < 64; i += NTHR) sm[OFF_BM + i] = bmsg[i];
    for (int i = tid; i < 256; i += NTHR) sm[OFF_BL + i] = blstm[i];
    if (tid < 32) { sm[OFF_TW + tid] = tw[tid]; sm[OFF_TB + tid] = tb[tid]; }
    __syncthreads();

    const int gw = blockIdx.x * NWARP + wid;
    float* sF = sm + OFF_FEAT + wid * 192;
    float* sMw = sm + OFF_M + wid * 128;

    int rem = EE;
    for (int wave = 0; wave < MAXWAVES; ++wave) {
        // phase A: min pending event id per touched node
        for (int e = blockIdx.x * NTHR + tid; e < EE; e += NBLK * NTHR) {
            if (!g_done[e]) {
                atomicMin(&g_nodemin[ei[e]], e);
                atomicMin(&g_nodemin[ei[EE + e]], e);
            }
        }
        grid_bar();
        // phase B: process ready events (warp per event)
        for (int e = gw; e < EE; e += TOTWARP) {
            if (g_done[e]) continue;
            int s = ei[e], d = ei[EE + e];
            if (g_nodemin[s] != e || g_nodemin[d] != e) continue;
            process_event(e, s, d, sm, sF, sMw, lane, eattr, etime);
            if (lane == 0) {
                g_done[e] = 1;
                g_nodemin[s] = 0x7fffffff;
                g_nodemin[d] = 0x7fffffff;
                atomicAdd(&g_remaining, -1);
            }
        }
        grid_bar();
        rem = *(volatile int*)&g_remaining;
        if (rem == 0) break;
    }

    // sequential fallback (uniform condition; ~never taken on this data)
    if (rem > 0) {
        if (blockIdx.x == 0 && wid == 0) {
            for (int e = 0; e < EE; ++e) {
                if (*(volatile int*)&g_done[e]) continue;
                int s = ei[e], d = ei[EE + e];
                process_event(e, s, d, sm, sF, sMw, lane, eattr, etime);
                __syncwarp();
                __threadfence_block();
                if (lane == 0) g_done[e] = 1;
                __syncwarp();
            }
        }
    }
    grid_bar();

    // ---- classifier: logits[e] = [h[dst] || x[dst]] @ Wc + bc (fused W_emb@W_cls) ----
    for (int i = tid; i < 192 * AA; i += NTHR) sm[OFF_WMT + i] = g_Wc[i];
    for (int i = tid; i < AA; i += NTHR) sm[OFF_WMT + 9600 + i] = g_bc[i];
    __syncthreads();
    const float* sWc = sm + OFF_WMT;
    const float* sBc = sm + OFF_WMT + 9600;

    for (int e = gw; e < EE; e += TOTWARP) {
        int d = ei[EE + e];
        __syncwarp();
        sF[lane]      = g_h[(size_t)d * HH + lane];
        sF[32 + lane] = g_h[(size_t)d * HH + 32 + lane];
        {
            const float4* xv = (const float4*)(x + (size_t)d * DF);
            ((float4*)(sF + 64))[lane] = xv[lane];
        }
        __syncwarp();
        float r0 = sBc[lane];
        float r1 = (lane < AA - 32) ? sBc[32 + lane] : 0.0f;
        const float4* fvc = (const float4*)sF;
#pragma unroll 4
        for (int q = 0; q < 48; ++q) {
            float4 f = fvc[q];
            int kb = 4 * q;
            r0 = fmaf(f.x, sWc[(kb + 0) * AA + lane], r0);
            r0 = fmaf(f.y, sWc[(kb + 1) * AA + lane], r0);
            r0 = fmaf(f.z, sWc[(kb + 2) * AA + lane], r0);
            r0 = fmaf(f.w, sWc[(kb + 3) * AA + lane], r0);
            r1 = fmaf(f.x, sWc[(kb + 0) * AA + 32 + lane], r1);
            r1 = fmaf(f.y, sWc[(kb + 1) * AA + 32 + lane], r1);
            r1 = fmaf(f.z, sWc[(kb + 2) * AA + 32 + lane], r1);
            r1 = fmaf(f.w, sWc[(kb + 3) * AA + 32 + lane], r1);
        }
        float* op = out + (size_t)e * AA;
        op[lane] = r0;
        if (lane < AA - 32) op[32 + lane] = r1;
    }
}

extern "C" void kernel_launch(void* const* d_in, const int* in_sizes, int n_in,
                              void* d_out, int out_size) {
    const float* x     = (const float*)d_in[0];
    const int*   ei    = (const int*)d_in[1];
    const float* eattr = (const float*)d_in[2];
    const float* etime = (const float*)d_in[3];
    const float* tw    = (const float*)d_in[4];
    const float* tb    = (const float*)d_in[5];
    const float* Wmsg  = (const float*)d_in[6];
    const float* bmsg  = (const float*)d_in[7];
    const float* Wih   = (const float*)d_in[8];
    const float* Whh   = (const float*)d_in[9];
    const float* blstm = (const float*)d_in[10];
    const float* Wemb  = (const float*)d_in[11];
    const float* bemb  = (const float*)d_in[12];
    const float* Wcls  = (const float*)d_in[13];
    const float* bcls  = (const float*)d_in[14];
    float* out = (float*)d_out;

    cudaFuncSetAttribute(k_persist, cudaFuncAttributeMaxDynamicSharedMemorySize, SMEM_BYTES);
    k_init<<<64, 256>>>(ei, Wemb, bemb, Wcls, bcls);
    k_persist<<<NBLK, NTHR, SMEM_BYTES>>>(x, ei, eattr, etime, tw, tb, Wmsg, bmsg, Wih, Whh,
                                          blstm, out);
}